// round 6
// baseline (speedup 1.0000x reference)
#include <cuda_runtime.h>
#include <cuda_bf16.h>

#define THICKNESS 0.00047f
#define MAX_V 1000000

__device__ float4 g_posw[MAX_V];   // padded vertices (x,y,z,0)
__device__ int g_pad_done = 0;     // pad blocks completed
__device__ int g_all_done = 0;     // blocks completed (for counter reset)

__device__ __forceinline__ float face_energy(
    float4 p0, float4 p1, float4 p2, float4 dm, float ar, float mu, float lam)
{
    float d1x = p0.x - p2.x, d1y = p0.y - p2.y, d1z = p0.z - p2.z;
    float d2x = p1.x - p2.x, d2y = p1.y - p2.y, d2z = p1.z - p2.z;
    float a = dm.x, b = dm.y, c = dm.z, d = dm.w;
    float F0x = d1x * a + d2x * c;
    float F0y = d1y * a + d2y * c;
    float F0z = d1z * a + d2z * c;
    float F1x = d1x * b + d2x * d;
    float F1y = d1y * b + d2y * d;
    float F1z = d1z * b + d2z * d;
    float g00 = 0.5f * (F0x * F0x + F0y * F0y + F0z * F0z - 1.0f);
    float g01 = 0.5f * (F0x * F1x + F0y * F1y + F0z * F1z);
    float g11 = 0.5f * (F1x * F1x + F1y * F1y + F1z * F1z - 1.0f);
    float tr = g00 + g11;
    float s00 = mu * g00 + 0.5f * lam * tr;
    float s01 = mu * g01;
    float s11 = mu * g11 + 0.5f * lam * tr;
    float ed = s00 * g00 + 2.0f * s01 * g01 + s11 * g11;
    return ar * THICKNESS * ed;
}

// Fused: pad blocks (bid < nPad) fill g_posw; face blocks prefetch streams,
// wait on g_pad_done, then gather + compute + scatter.
__global__ __launch_bounds__(256, 6)
void stvk_fused_kernel(
    const float* __restrict__ pos,        // [V,3]
    const int* __restrict__ faces,        // [F,3] int32
    const float* __restrict__ dminv,      // [F,2,2]
    const float* __restrict__ area,       // [F,1]
    const float* __restrict__ mu_p,
    const float* __restrict__ lam_p,
    float* __restrict__ per_vert,         // [V]
    float* __restrict__ loss,
    int V, int F, int nPad)
{
    int tid = threadIdx.x;

    if ((int)blockIdx.x < nPad) {
        // ---- pad path: 8 vertices per thread ----
        int v0 = (blockIdx.x * 256 + tid) * 8;
        if (v0 + 8 <= V) {
            const float4* p = (const float4*)(pos + 3 * v0);  // 96B, 16B-aligned
            float4 q[6];
            #pragma unroll
            for (int k = 0; k < 6; k++) q[k] = __ldcs(p + k);
            const float* s = (const float*)q;
            #pragma unroll
            for (int k = 0; k < 8; k++)
                g_posw[v0 + k] = make_float4(s[3 * k], s[3 * k + 1], s[3 * k + 2], 0.0f);
        } else {
            for (int v = v0; v < V; v++) {
                const float* b = pos + 3 * v;
                g_posw[v] = make_float4(b[0], b[1], b[2], 0.0f);
            }
        }
        __threadfence();
        __syncthreads();
        if (tid == 0) atomicAdd(&g_pad_done, 1);
    } else {
        // ---- face path: 2 faces per thread ----
        int F2 = F >> 1;
        int t = (blockIdx.x - nPad) * 256 + tid;
        float esum = 0.0f;

        int i00 = 0, i01 = 0, i02 = 0, i10 = 0, i11 = 0, i12 = 0;
        float4 dm0, dm1;
        float ar0 = 0.0f, ar1 = 0.0f;
        int nf = 0;  // 0, 1, or 2 faces for this thread

        if (t < F2) {
            // 2 faces: 24B of indices, 8B-aligned
            const int2* fp = (const int2*)(faces + 6 * t);
            int2 a = __ldcs(fp);
            int2 b = __ldcs(fp + 1);
            int2 c = __ldcs(fp + 2);
            i00 = a.x; i01 = a.y; i02 = b.x;
            i10 = b.y; i11 = c.x; i12 = c.y;
            dm0 = __ldcs((const float4*)dminv + 2 * t);
            dm1 = __ldcs((const float4*)dminv + 2 * t + 1);
            float2 arv = __ldcs((const float2*)(area + 2 * t));
            ar0 = arv.x; ar1 = arv.y;
            nf = 2;
        } else if (t == F2 && (F & 1)) {
            int f = F - 1;
            const int* fr = faces + 3 * f;
            i00 = fr[0]; i01 = fr[1]; i02 = fr[2];
            dm0 = __ldg((const float4*)dminv + f);
            ar0 = __ldg(&area[f]);
            nf = 1;
        }
        float mu = __ldg(mu_p);
        float lam = __ldg(lam_p);

        // wait for padding to finish (wave-1 face blocks overlap their
        // stream loads above with the pad blocks' work)
        if (tid == 0) {
            while (*(volatile int*)&g_pad_done < nPad) __nanosleep(64);
            __threadfence();
        }
        __syncthreads();

        if (nf > 0) {
            float4 p00 = __ldg(&g_posw[i00]);
            float4 p01 = __ldg(&g_posw[i01]);
            float4 p02 = __ldg(&g_posw[i02]);
            if (nf == 2) {
                float4 p10 = __ldg(&g_posw[i10]);
                float4 p11 = __ldg(&g_posw[i11]);
                float4 p12 = __ldg(&g_posw[i12]);
                float e0 = face_energy(p00, p01, p02, dm0, ar0, mu, lam);
                float e1 = face_energy(p10, p11, p12, dm1, ar1, mu, lam);
                esum = e0 + e1;
                float e03 = e0 * (1.0f / 3.0f);
                float e13 = e1 * (1.0f / 3.0f);
                atomicAdd(&per_vert[i00], e03);
                atomicAdd(&per_vert[i01], e03);
                atomicAdd(&per_vert[i02], e03);
                atomicAdd(&per_vert[i10], e13);
                atomicAdd(&per_vert[i11], e13);
                atomicAdd(&per_vert[i12], e13);
            } else {
                float e0 = face_energy(p00, p01, p02, dm0, ar0, mu, lam);
                esum = e0;
                float e03 = e0 * (1.0f / 3.0f);
                atomicAdd(&per_vert[i00], e03);
                atomicAdd(&per_vert[i01], e03);
                atomicAdd(&per_vert[i02], e03);
            }
        }

        // block-reduce esum -> one loss atomic per face block
        float v = esum;
        #pragma unroll
        for (int off = 16; off > 0; off >>= 1)
            v += __shfl_down_sync(0xFFFFFFFFu, v, off);
        __shared__ float smem[8];
        int lane = tid & 31;
        int wid = tid >> 5;
        if (lane == 0) smem[wid] = v;
        __syncthreads();
        if (wid == 0) {
            float w = (lane < 8) ? smem[lane] : 0.0f;
            #pragma unroll
            for (int off = 4; off > 0; off >>= 1)
                w += __shfl_down_sync(0xFFFFFFFFu, w, off);
            if (lane == 0 && loss != nullptr)
                atomicAdd(loss, w);
        }
    }

    // replay-safe counter reset: last block out zeroes the counters
    if (tid == 0) {
        int d = atomicAdd(&g_all_done, 1);
        if (d == (int)gridDim.x - 1) {
            atomicExch(&g_pad_done, 0);
            atomicExch(&g_all_done, 0);
        }
    }
}

extern "C" void kernel_launch(void* const* d_in, const int* in_sizes, int n_in,
                              void* d_out, int out_size) {
    const float* pos = (const float*)d_in[0];
    const int* faces = (const int*)d_in[1];
    const float* dminv = (const float*)d_in[2];
    const float* area = (const float*)d_in[3];
    const float* mu_p = (const float*)d_in[4];
    const float* lam_p = (const float*)d_in[5];

    int V = in_sizes[0] / 3;
    int F = in_sizes[1] / 3;

    float* out = (float*)d_out;
    float* per_vert = out + (out_size - V);
    float* loss = (out_size > V) ? out : nullptr;

    cudaMemsetAsync(d_out, 0, (size_t)out_size * sizeof(float));

    int nPad = (V + 2047) / 2048;                 // 8 verts/thread, 256 thr
    int faceThreads = (F >> 1) + (F & 1);         // 2 faces/thread
    int nFace = (faceThreads + 255) / 256;
    stvk_fused_kernel<<<nPad + nFace, 256>>>(
        pos, faces, dminv, area, mu_p, lam_p, per_vert, loss, V, F, nPad);
}

// round 7
// speedup vs baseline: 1.2121x; 1.2121x over previous
#include <cuda_runtime.h>
#include <cuda_bf16.h>

#define THICKNESS 0.00047f
#define MAX_V 1000000

__device__ float4 g_posw[MAX_V];   // padded vertices (x,y,z,0): 1-sector gathers

// Pad pos -> float4 AND zero the output buffer (replaces cudaMemset node).
// 4 vertices per thread via 3 aligned float4 loads; grid-stride.
__global__ __launch_bounds__(256)
void pad_and_zero_kernel(const float* __restrict__ pos, float* __restrict__ outbuf,
                         int V, int outElems) {
    int nthreads = gridDim.x * blockDim.x;
    int tid = blockIdx.x * blockDim.x + threadIdx.x;

    // zero output: float4 grid-stride + scalar tail by thread 0
    int out4 = outElems >> 2;
    for (int j = tid; j < out4; j += nthreads)
        ((float4*)outbuf)[j] = make_float4(0.f, 0.f, 0.f, 0.f);
    if (tid == 0)
        for (int j = out4 << 2; j < outElems; j++) outbuf[j] = 0.0f;

    // pad vertices: 4 per iteration (48B = 3 float4), grid-stride
    int V4 = V >> 2;
    for (int j = tid; j < V4; j += nthreads) {
        const float4* p = (const float4*)(pos + 12ll * j);
        float4 a = __ldcs(p);
        float4 b = __ldcs(p + 1);
        float4 c = __ldcs(p + 2);
        int v = 4 * j;
        g_posw[v + 0] = make_float4(a.x, a.y, a.z, 0.0f);
        g_posw[v + 1] = make_float4(a.w, b.x, b.y, 0.0f);
        g_posw[v + 2] = make_float4(b.z, b.w, c.x, 0.0f);
        g_posw[v + 3] = make_float4(c.y, c.z, c.w, 0.0f);
    }
    if (tid == 0)
        for (int v = V4 << 2; v < V; v++) {
            const float* b = pos + 3ll * v;
            g_posw[v] = make_float4(b[0], b[1], b[2], 0.0f);
        }
}

__global__ __launch_bounds__(256)
void stvk_face_kernel(
    const int* __restrict__ faces,        // [F,3] int32
    const float* __restrict__ dminv,      // [F,2,2]
    const float* __restrict__ area,       // [F,1]
    const float* __restrict__ mu_p,
    const float* __restrict__ lam_p,
    float* __restrict__ per_vert,         // [V]
    float* __restrict__ loss,
    int F)
{
    int f = blockIdx.x * blockDim.x + threadIdx.x;
    float e = 0.0f;
    if (f < F) {
        // faces row (12B @ 4-align): parity-aligned int2+int, evict-first
        bool feven = (f & 1) == 0;
        const int* frow = faces + 3u * (unsigned)f;
        int2 fab = __ldcs((const int2*)(frow + (feven ? 0 : 1)));
        int  fc  = __ldcs(frow + (feven ? 2 : 0));
        int i0 = feven ? fab.x : fc;
        int i1 = feven ? fab.y : fab.x;
        int i2 = feven ? fc    : fab.y;

        // single-sector 16B gathers (L2-resident padded array)
        float4 p0 = __ldg(&g_posw[i0]);
        float4 p1 = __ldg(&g_posw[i1]);
        float4 p2 = __ldg(&g_posw[i2]);

        float d1x = p0.x - p2.x, d1y = p0.y - p2.y, d1z = p0.z - p2.z;
        float d2x = p1.x - p2.x, d2y = p1.y - p2.y, d2z = p1.z - p2.z;

        float4 dm = __ldcs((const float4*)(dminv) + f);
        float a = dm.x, b = dm.y, c = dm.z, d = dm.w;

        float F0x = d1x * a + d2x * c;
        float F0y = d1y * a + d2y * c;
        float F0z = d1z * a + d2z * c;
        float F1x = d1x * b + d2x * d;
        float F1y = d1y * b + d2y * d;
        float F1z = d1z * b + d2z * d;

        float g00 = 0.5f * (F0x * F0x + F0y * F0y + F0z * F0z - 1.0f);
        float g01 = 0.5f * (F0x * F1x + F0y * F1y + F0z * F1z);
        float g11 = 0.5f * (F1x * F1x + F1y * F1y + F1z * F1z - 1.0f);
        float tr = g00 + g11;

        float mu = __ldg(mu_p);
        float lam = __ldg(lam_p);

        float s00 = mu * g00 + 0.5f * lam * tr;
        float s01 = mu * g01;
        float s11 = mu * g11 + 0.5f * lam * tr;

        float ed = s00 * g00 + 2.0f * s01 * g01 + s11 * g11;

        e = __ldcs(&area[f]) * THICKNESS * ed;

        float e3 = e * (1.0f / 3.0f);
        atomicAdd(&per_vert[i0], e3);
        atomicAdd(&per_vert[i1], e3);
        atomicAdd(&per_vert[i2], e3);
    }

    // block-reduce -> one loss atomic per block
    float v = e;
    #pragma unroll
    for (int off = 16; off > 0; off >>= 1)
        v += __shfl_down_sync(0xFFFFFFFFu, v, off);

    __shared__ float smem[8];
    int lane = threadIdx.x & 31;
    int wid = threadIdx.x >> 5;
    if (lane == 0) smem[wid] = v;
    __syncthreads();
    if (wid == 0) {
        float w = (lane < (blockDim.x >> 5)) ? smem[lane] : 0.0f;
        #pragma unroll
        for (int off = 4; off > 0; off >>= 1)
            w += __shfl_down_sync(0xFFFFFFFFu, w, off);
        if (lane == 0 && loss != nullptr)
            atomicAdd(loss, w);
    }
}

extern "C" void kernel_launch(void* const* d_in, const int* in_sizes, int n_in,
                              void* d_out, int out_size) {
    const float* pos = (const float*)d_in[0];
    const int* faces = (const int*)d_in[1];
    const float* dminv = (const float*)d_in[2];
    const float* area = (const float*)d_in[3];
    const float* mu_p = (const float*)d_in[4];
    const float* lam_p = (const float*)d_in[5];

    int V = in_sizes[0] / 3;
    int F = in_sizes[1] / 3;

    float* out = (float*)d_out;
    float* per_vert = out + (out_size - V);
    float* loss = (out_size > V) ? out : nullptr;

    // prepass: pad pos + zero output. Many CTAs for full BW.
    int padBlocks = 2048;  // grid-stride; ~524K threads
    pad_and_zero_kernel<<<padBlocks, 256>>>(pos, out, V, out_size);

    int blocks = (F + 255) / 256;
    stvk_face_kernel<<<blocks, 256>>>(faces, dminv, area, mu_p, lam_p,
                                      per_vert, loss, F);
}

// round 8
// speedup vs baseline: 1.2393x; 1.0224x over previous
#include <cuda_runtime.h>
#include <cuda_bf16.h>

#define THICKNESS 0.00047f
#define MAX_V 1000000

__device__ float4 g_posw[MAX_V];   // padded vertices (x,y,z,0): 1-sector gathers

// 1 vertex per thread, maximum TLP. Parity-aligned 12B read (coalesced across
// the warp: lanes cover 384 contiguous bytes), one coalesced 16B store.
__global__ __launch_bounds__(256)
void pad_pos_kernel(const float* __restrict__ pos, int V) {
    int i = blockIdx.x * blockDim.x + threadIdx.x;
    if (i >= V) return;
    bool even = (i & 1) == 0;
    const float* base = pos + 3u * (unsigned)i;
    float2 ab = __ldcs((const float2*)(base + (even ? 0 : 1)));
    float  c  = __ldcs(base + (even ? 2 : 0));
    float x = even ? ab.x : c;
    float y = even ? ab.y : ab.x;
    float z = even ? c    : ab.y;
    g_posw[i] = make_float4(x, y, z, 0.0f);
}

__global__ __launch_bounds__(256)
void stvk_face_kernel(
    const int* __restrict__ faces,        // [F,3] int32
    const float* __restrict__ dminv,      // [F,2,2]
    const float* __restrict__ area,       // [F,1]
    const float* __restrict__ mu_p,
    const float* __restrict__ lam_p,
    float* __restrict__ per_vert,         // [V]
    float* __restrict__ loss,
    int F)
{
    int f = blockIdx.x * blockDim.x + threadIdx.x;
    float e = 0.0f;
    if (f < F) {
        // faces row (12B @ 4-align): parity-aligned int2+int, evict-first
        bool feven = (f & 1) == 0;
        const int* frow = faces + 3u * (unsigned)f;
        int2 fab = __ldcs((const int2*)(frow + (feven ? 0 : 1)));
        int  fc  = __ldcs(frow + (feven ? 2 : 0));
        int i0 = feven ? fab.x : fc;
        int i1 = feven ? fab.y : fab.x;
        int i2 = feven ? fc    : fab.y;

        // single-sector 16B gathers (L2-resident padded array)
        float4 p0 = __ldg(&g_posw[i0]);
        float4 p1 = __ldg(&g_posw[i1]);
        float4 p2 = __ldg(&g_posw[i2]);

        float d1x = p0.x - p2.x, d1y = p0.y - p2.y, d1z = p0.z - p2.z;
        float d2x = p1.x - p2.x, d2y = p1.y - p2.y, d2z = p1.z - p2.z;

        float4 dm = __ldcs((const float4*)(dminv) + f);
        float a = dm.x, b = dm.y, c = dm.z, d = dm.w;

        float F0x = d1x * a + d2x * c;
        float F0y = d1y * a + d2y * c;
        float F0z = d1z * a + d2z * c;
        float F1x = d1x * b + d2x * d;
        float F1y = d1y * b + d2y * d;
        float F1z = d1z * b + d2z * d;

        float g00 = 0.5f * (F0x * F0x + F0y * F0y + F0z * F0z - 1.0f);
        float g01 = 0.5f * (F0x * F1x + F0y * F1y + F0z * F1z);
        float g11 = 0.5f * (F1x * F1x + F1y * F1y + F1z * F1z - 1.0f);
        float tr = g00 + g11;

        float mu = __ldg(mu_p);
        float lam = __ldg(lam_p);

        float s00 = mu * g00 + 0.5f * lam * tr;
        float s01 = mu * g01;
        float s11 = mu * g11 + 0.5f * lam * tr;

        float ed = s00 * g00 + 2.0f * s01 * g01 + s11 * g11;

        e = __ldcs(&area[f]) * THICKNESS * ed;

        float e3 = e * (1.0f / 3.0f);
        atomicAdd(&per_vert[i0], e3);
        atomicAdd(&per_vert[i1], e3);
        atomicAdd(&per_vert[i2], e3);
    }

    // block-reduce -> one loss atomic per block
    float v = e;
    #pragma unroll
    for (int off = 16; off > 0; off >>= 1)
        v += __shfl_down_sync(0xFFFFFFFFu, v, off);

    __shared__ float smem[8];
    int lane = threadIdx.x & 31;
    int wid = threadIdx.x >> 5;
    if (lane == 0) smem[wid] = v;
    __syncthreads();
    if (wid == 0) {
        float w = (lane < (blockDim.x >> 5)) ? smem[lane] : 0.0f;
        #pragma unroll
        for (int off = 4; off > 0; off >>= 1)
            w += __shfl_down_sync(0xFFFFFFFFu, w, off);
        if (lane == 0 && loss != nullptr)
            atomicAdd(loss, w);
    }
}

extern "C" void kernel_launch(void* const* d_in, const int* in_sizes, int n_in,
                              void* d_out, int out_size) {
    const float* pos = (const float*)d_in[0];
    const int* faces = (const int*)d_in[1];
    const float* dminv = (const float*)d_in[2];
    const float* area = (const float*)d_in[3];
    const float* mu_p = (const float*)d_in[4];
    const float* lam_p = (const float*)d_in[5];

    int V = in_sizes[0] / 3;
    int F = in_sizes[1] / 3;

    float* out = (float*)d_out;
    float* per_vert = out + (out_size - V);
    float* loss = (out_size > V) ? out : nullptr;

    cudaMemsetAsync(d_out, 0, (size_t)out_size * sizeof(float));

    pad_pos_kernel<<<(V + 255) / 256, 256>>>(pos, V);

    int blocks = (F + 255) / 256;
    stvk_face_kernel<<<blocks, 256>>>(faces, dminv, area, mu_p, lam_p,
                                      per_vert, loss, F);
}

// round 9
// speedup vs baseline: 1.2400x; 1.0005x over previous
#include <cuda_runtime.h>
#include <cuda_bf16.h>

#define THICKNESS 0.00047f
#define MAX_V 1000000

__device__ float4 g_posw[MAX_V];   // padded vertices (x,y,z,0): 1-sector gathers

// 1 vertex per thread + zero one output element per thread.
// Ends with threadfence + PDL trigger so the face kernel can overlap.
__global__ __launch_bounds__(256)
void pad_pos_kernel(const float* __restrict__ pos, float* __restrict__ outbuf,
                    int V, int outElems) {
    int i = blockIdx.x * blockDim.x + threadIdx.x;
    if (i < outElems) outbuf[i] = 0.0f;
    if (i < V) {
        bool even = (i & 1) == 0;
        const float* base = pos + 3u * (unsigned)i;
        float2 ab = __ldcs((const float2*)(base + (even ? 0 : 1)));
        float  c  = __ldcs(base + (even ? 2 : 0));
        float x = even ? ab.x : c;
        float y = even ? ab.y : ab.x;
        float z = even ? c    : ab.y;
        g_posw[i] = make_float4(x, y, z, 0.0f);
    }
    __threadfence();
    cudaTriggerProgrammaticLaunchCompletion();
}

__global__ __launch_bounds__(256)
void stvk_face_kernel(
    const int* __restrict__ faces,        // [F,3] int32
    const float* __restrict__ dminv,      // [F,2,2]
    const float* __restrict__ area,       // [F,1]
    const float* __restrict__ mu_p,
    const float* __restrict__ lam_p,
    float* __restrict__ per_vert,         // [V]
    float* __restrict__ loss,
    int F)
{
    int f = blockIdx.x * blockDim.x + threadIdx.x;

    // ---- phase 1: pad-independent streaming loads (overlap PDL primary) ----
    int i0 = 0, i1 = 0, i2 = 0;
    float4 dm = make_float4(0.f, 0.f, 0.f, 0.f);
    float arv = 0.0f;
    if (f < F) {
        bool feven = (f & 1) == 0;
        const int* frow = faces + 3u * (unsigned)f;
        int2 fab = __ldcs((const int2*)(frow + (feven ? 0 : 1)));
        int  fc  = __ldcs(frow + (feven ? 2 : 0));
        i0 = feven ? fab.x : fc;
        i1 = feven ? fab.y : fab.x;
        i2 = feven ? fc    : fab.y;
        dm = __ldcs((const float4*)(dminv) + f);
        arv = __ldcs(&area[f]);
    }
    float mu = __ldg(mu_p);
    float lam = __ldg(lam_p);

    // ---- wait for pad kernel's writes to be visible ----
    cudaGridDependencySynchronize();

    float e = 0.0f;
    if (f < F) {
        float4 p0 = __ldg(&g_posw[i0]);
        float4 p1 = __ldg(&g_posw[i1]);
        float4 p2 = __ldg(&g_posw[i2]);

        float d1x = p0.x - p2.x, d1y = p0.y - p2.y, d1z = p0.z - p2.z;
        float d2x = p1.x - p2.x, d2y = p1.y - p2.y, d2z = p1.z - p2.z;

        float a = dm.x, b = dm.y, c = dm.z, d = dm.w;
        float F0x = d1x * a + d2x * c;
        float F0y = d1y * a + d2y * c;
        float F0z = d1z * a + d2z * c;
        float F1x = d1x * b + d2x * d;
        float F1y = d1y * b + d2y * d;
        float F1z = d1z * b + d2z * d;

        float g00 = 0.5f * (F0x * F0x + F0y * F0y + F0z * F0z - 1.0f);
        float g01 = 0.5f * (F0x * F1x + F0y * F1y + F0z * F1z);
        float g11 = 0.5f * (F1x * F1x + F1y * F1y + F1z * F1z - 1.0f);
        float tr = g00 + g11;

        float s00 = mu * g00 + 0.5f * lam * tr;
        float s01 = mu * g01;
        float s11 = mu * g11 + 0.5f * lam * tr;

        float ed = s00 * g00 + 2.0f * s01 * g01 + s11 * g11;
        e = arv * THICKNESS * ed;

        float e3 = e * (1.0f / 3.0f);
        atomicAdd(&per_vert[i0], e3);
        atomicAdd(&per_vert[i1], e3);
        atomicAdd(&per_vert[i2], e3);
    }

    // block-reduce -> one loss atomic per block
    float v = e;
    #pragma unroll
    for (int off = 16; off > 0; off >>= 1)
        v += __shfl_down_sync(0xFFFFFFFFu, v, off);

    __shared__ float smem[8];
    int lane = threadIdx.x & 31;
    int wid = threadIdx.x >> 5;
    if (lane == 0) smem[wid] = v;
    __syncthreads();
    if (wid == 0) {
        float w = (lane < (blockDim.x >> 5)) ? smem[lane] : 0.0f;
        #pragma unroll
        for (int off = 4; off > 0; off >>= 1)
            w += __shfl_down_sync(0xFFFFFFFFu, w, off);
        if (lane == 0 && loss != nullptr)
            atomicAdd(loss, w);
    }
}

extern "C" void kernel_launch(void* const* d_in, const int* in_sizes, int n_in,
                              void* d_out, int out_size) {
    const float* pos = (const float*)d_in[0];
    const int* faces = (const int*)d_in[1];
    const float* dminv = (const float*)d_in[2];
    const float* area = (const float*)d_in[3];
    const float* mu_p = (const float*)d_in[4];
    const float* lam_p = (const float*)d_in[5];

    int V = in_sizes[0] / 3;
    int F = in_sizes[1] / 3;

    float* out = (float*)d_out;
    float* per_vert = out + (out_size - V);
    float* loss = (out_size > V) ? out : nullptr;

    // primary: pad + zero output (no separate memset node)
    int padThreads = (out_size > V) ? out_size : V;
    pad_pos_kernel<<<(padThreads + 255) / 256, 256>>>(pos, out, V, out_size);

    // secondary: PDL — launches early, overlaps streaming loads with pad
    cudaLaunchConfig_t cfg = {};
    cfg.gridDim = dim3((F + 255) / 256, 1, 1);
    cfg.blockDim = dim3(256, 1, 1);
    cfg.dynamicSmemBytes = 0;
    cfg.stream = 0;  // legacy default stream (same as <<<>>>)
    cudaLaunchAttribute attrs[1];
    attrs[0].id = cudaLaunchAttributeProgrammaticStreamSerialization;
    attrs[0].val.programmaticStreamSerializationAllowed = 1;
    cfg.attrs = attrs;
    cfg.numAttrs = 1;
    cudaLaunchKernelEx(&cfg, stvk_face_kernel,
                       faces, dminv, area, mu_p, lam_p, per_vert, loss, F);
}

// round 10
// speedup vs baseline: 1.2782x; 1.0309x over previous
#include <cuda_runtime.h>
#include <cuda_bf16.h>

#define THICKNESS 0.00047f

// faces row loader: 12B @ 4-align, parity-aligned int2+int (each load 1 sector)
__device__ __forceinline__ void load_face_row(const int* __restrict__ faces, int f,
                                              int& i0, int& i1, int& i2) {
    bool feven = (f & 1) == 0;
    const int* frow = faces + 3u * (unsigned)f;
    int2 fab = __ldcs((const int2*)(frow + (feven ? 0 : 1)));
    int  fc  = __ldcs(frow + (feven ? 2 : 0));
    i0 = feven ? fab.x : fc;
    i1 = feven ? fab.y : fab.x;
    i2 = feven ? fc    : fab.y;
}

// vertex loader: parity-aligned float2+float (no straddle per load; L1 merges)
__device__ __forceinline__ void load_vert(const float* __restrict__ pos, int i,
                                          float& x, float& y, float& z) {
    bool even = (i & 1) == 0;
    const float* base = pos + 3u * (unsigned)i;
    float2 ab = __ldg((const float2*)(base + (even ? 0 : 1)));
    float  c  = __ldg(base + (even ? 2 : 0));
    x = even ? ab.x : c;
    y = even ? ab.y : ab.x;
    z = even ? c    : ab.y;
}

__device__ __forceinline__ float stvk_energy(
    float p0x, float p0y, float p0z,
    float p1x, float p1y, float p1z,
    float p2x, float p2y, float p2z,
    float4 dm, float ar, float mu, float lam)
{
    float d1x = p0x - p2x, d1y = p0y - p2y, d1z = p0z - p2z;
    float d2x = p1x - p2x, d2y = p1y - p2y, d2z = p1z - p2z;
    float a = dm.x, b = dm.y, c = dm.z, d = dm.w;
    float F0x = d1x * a + d2x * c;
    float F0y = d1y * a + d2y * c;
    float F0z = d1z * a + d2z * c;
    float F1x = d1x * b + d2x * d;
    float F1y = d1y * b + d2y * d;
    float F1z = d1z * b + d2z * d;
    float g00 = 0.5f * (F0x * F0x + F0y * F0y + F0z * F0z - 1.0f);
    float g01 = 0.5f * (F0x * F1x + F0y * F1y + F0z * F1z);
    float g11 = 0.5f * (F1x * F1x + F1y * F1y + F1z * F1z - 1.0f);
    float tr = g00 + g11;
    float s00 = mu * g00 + 0.5f * lam * tr;
    float s01 = mu * g01;
    float s11 = mu * g11 + 0.5f * lam * tr;
    float ed = s00 * g00 + 2.0f * s01 * g01 + s11 * g11;
    return ar * THICKNESS * ed;
}

// 2 faces per thread (fA = t, fB = t + S), fully scalar, all loads front-loaded.
__global__ __launch_bounds__(256, 6)
void stvk_face2_kernel(
    const float* __restrict__ pos,        // [V,3]
    const int* __restrict__ faces,        // [F,3] int32
    const float* __restrict__ dminv,      // [F,2,2]
    const float* __restrict__ area,       // [F,1]
    const float* __restrict__ mu_p,
    const float* __restrict__ lam_p,
    float* __restrict__ per_vert,         // [V]
    float* __restrict__ loss,
    int F, int S)                          // S = ceil(F/2)
{
    int t = blockIdx.x * blockDim.x + threadIdx.x;
    float esum = 0.0f;
    float mu = __ldg(mu_p);
    float lam = __ldg(lam_p);

    if (t < S) {
        int fA = t;
        int fB = t + S;
        bool hasB = fB < F;
        int fBs = hasB ? fB : fA;   // safe address for speculative loads

        // ---- streams for both faces ----
        int a0, a1, a2, b0, b1, b2;
        load_face_row(faces, fA, a0, a1, a2);
        load_face_row(faces, fBs, b0, b1, b2);
        float4 dmA = __ldcs((const float4*)dminv + fA);
        float4 dmB = __ldcs((const float4*)dminv + fBs);
        float arA = __ldcs(&area[fA]);
        float arB = __ldcs(&area[fBs]);

        // ---- 12 gather loads in flight ----
        float A0x, A0y, A0z, A1x, A1y, A1z, A2x, A2y, A2z;
        float B0x, B0y, B0z, B1x, B1y, B1z, B2x, B2y, B2z;
        load_vert(pos, a0, A0x, A0y, A0z);
        load_vert(pos, a1, A1x, A1y, A1z);
        load_vert(pos, a2, A2x, A2y, A2z);
        load_vert(pos, b0, B0x, B0y, B0z);
        load_vert(pos, b1, B1x, B1y, B1z);
        load_vert(pos, b2, B2x, B2y, B2z);

        // ---- compute + scatter A ----
        float eA = stvk_energy(A0x, A0y, A0z, A1x, A1y, A1z, A2x, A2y, A2z,
                               dmA, arA, mu, lam);
        esum += eA;
        float eA3 = eA * (1.0f / 3.0f);
        atomicAdd(&per_vert[a0], eA3);
        atomicAdd(&per_vert[a1], eA3);
        atomicAdd(&per_vert[a2], eA3);

        // ---- compute + scatter B ----
        if (hasB) {
            float eB = stvk_energy(B0x, B0y, B0z, B1x, B1y, B1z, B2x, B2y, B2z,
                                   dmB, arB, mu, lam);
            esum += eB;
            float eB3 = eB * (1.0f / 3.0f);
            atomicAdd(&per_vert[b0], eB3);
            atomicAdd(&per_vert[b1], eB3);
            atomicAdd(&per_vert[b2], eB3);
        }
    }

    // block-reduce -> one loss atomic per block
    float v = esum;
    #pragma unroll
    for (int off = 16; off > 0; off >>= 1)
        v += __shfl_down_sync(0xFFFFFFFFu, v, off);

    __shared__ float smem[8];
    int lane = threadIdx.x & 31;
    int wid = threadIdx.x >> 5;
    if (lane == 0) smem[wid] = v;
    __syncthreads();
    if (wid == 0) {
        float w = (lane < (blockDim.x >> 5)) ? smem[lane] : 0.0f;
        #pragma unroll
        for (int off = 4; off > 0; off >>= 1)
            w += __shfl_down_sync(0xFFFFFFFFu, w, off);
        if (lane == 0 && loss != nullptr)
            atomicAdd(loss, w);
    }
}

extern "C" void kernel_launch(void* const* d_in, const int* in_sizes, int n_in,
                              void* d_out, int out_size) {
    const float* pos = (const float*)d_in[0];
    const int* faces = (const int*)d_in[1];
    const float* dminv = (const float*)d_in[2];
    const float* area = (const float*)d_in[3];
    const float* mu_p = (const float*)d_in[4];
    const float* lam_p = (const float*)d_in[5];

    int V = in_sizes[0] / 3;
    int F = in_sizes[1] / 3;

    float* out = (float*)d_out;
    float* per_vert = out + (out_size - V);
    float* loss = (out_size > V) ? out : nullptr;

    cudaMemsetAsync(d_out, 0, (size_t)out_size * sizeof(float));

    int S = (F + 1) / 2;                // faces per half
    int blocks = (S + 255) / 256;
    stvk_face2_kernel<<<blocks, 256>>>(pos, faces, dminv, area, mu_p, lam_p,
                                       per_vert, loss, F, S);
}

// round 11
// speedup vs baseline: 1.2832x; 1.0039x over previous
#include <cuda_runtime.h>
#include <cuda_bf16.h>

#define THICKNESS 0.00047f

// Merged gather: row [3i, 3i+3) fits one aligned float4 iff (3i)&3 <= 1
// (i = 0,3 mod 4; also guaranteed no 32B-sector straddle in that case).
// Otherwise parity float2+float (2 loads).
__device__ __forceinline__ float3 load_vert(const float* __restrict__ pos, int i) {
    unsigned base = 3u * (unsigned)i;
    unsigned off = base & 3u;
    float x, y, z;
    if (off <= 1u) {
        float4 q = __ldg((const float4*)(pos + (base & ~3u)));
        x = off ? q.y : q.x;
        y = off ? q.z : q.y;
        z = off ? q.w : q.z;
    } else {
        bool o2 = (off == 2u);
        float2 ab = __ldg((const float2*)(pos + base + (o2 ? 0u : 1u)));
        float  c  = __ldg(pos + base + (o2 ? 2u : 0u));
        x = o2 ? ab.x : c;
        y = o2 ? ab.y : ab.x;
        z = o2 ? c    : ab.y;
    }
    return make_float3(x, y, z);
}

__global__ __launch_bounds__(256)
void stvk_face_kernel(
    const float* __restrict__ pos,        // [V,3]
    const int* __restrict__ faces,        // [F,3] int32
    const float* __restrict__ dminv,      // [F,2,2]
    const float* __restrict__ area,       // [F,1]
    const float* __restrict__ mu_p,
    const float* __restrict__ lam_p,
    float* __restrict__ per_vert,         // [V]
    float* __restrict__ loss,
    int F)
{
    int f = blockIdx.x * blockDim.x + threadIdx.x;
    float e = 0.0f;
    if (f < F) {
        // faces row (12B @ 4-align): parity int2+int, evict-first
        bool feven = (f & 1) == 0;
        const int* frow = faces + 3u * (unsigned)f;
        int2 fab = __ldcs((const int2*)(frow + (feven ? 0 : 1)));
        int  fc  = __ldcs(frow + (feven ? 2 : 0));
        int i0 = feven ? fab.x : fc;
        int i1 = feven ? fab.y : fab.x;
        int i2 = feven ? fc    : fab.y;

        float3 p0 = load_vert(pos, i0);
        float3 p1 = load_vert(pos, i1);
        float3 p2 = load_vert(pos, i2);

        float d1x = p0.x - p2.x, d1y = p0.y - p2.y, d1z = p0.z - p2.z;
        float d2x = p1.x - p2.x, d2y = p1.y - p2.y, d2z = p1.z - p2.z;

        float4 dm = __ldcs((const float4*)(dminv) + f);
        float a = dm.x, b = dm.y, c = dm.z, d = dm.w;

        float F0x = d1x * a + d2x * c;
        float F0y = d1y * a + d2y * c;
        float F0z = d1z * a + d2z * c;
        float F1x = d1x * b + d2x * d;
        float F1y = d1y * b + d2y * d;
        float F1z = d1z * b + d2z * d;

        float g00 = 0.5f * (F0x * F0x + F0y * F0y + F0z * F0z - 1.0f);
        float g01 = 0.5f * (F0x * F1x + F0y * F1y + F0z * F1z);
        float g11 = 0.5f * (F1x * F1x + F1y * F1y + F1z * F1z - 1.0f);
        float tr = g00 + g11;

        float mu = __ldg(mu_p);
        float lam = __ldg(lam_p);

        float s00 = mu * g00 + 0.5f * lam * tr;
        float s01 = mu * g01;
        float s11 = mu * g11 + 0.5f * lam * tr;

        float ed = s00 * g00 + 2.0f * s01 * g01 + s11 * g11;

        e = __ldcs(&area[f]) * THICKNESS * ed;

        float e3 = e * (1.0f / 3.0f);
        atomicAdd(&per_vert[i0], e3);
        atomicAdd(&per_vert[i1], e3);
        atomicAdd(&per_vert[i2], e3);
    }

    // block-reduce -> one loss atomic per block
    float v = e;
    #pragma unroll
    for (int off = 16; off > 0; off >>= 1)
        v += __shfl_down_sync(0xFFFFFFFFu, v, off);

    __shared__ float smem[8];
    int lane = threadIdx.x & 31;
    int wid = threadIdx.x >> 5;
    if (lane == 0) smem[wid] = v;
    __syncthreads();
    if (wid == 0) {
        float w = (lane < (blockDim.x >> 5)) ? smem[lane] : 0.0f;
        #pragma unroll
        for (int off = 4; off > 0; off >>= 1)
            w += __shfl_down_sync(0xFFFFFFFFu, w, off);
        if (lane == 0 && loss != nullptr)
            atomicAdd(loss, w);
    }
}

extern "C" void kernel_launch(void* const* d_in, const int* in_sizes, int n_in,
                              void* d_out, int out_size) {
    const float* pos = (const float*)d_in[0];
    const int* faces = (const int*)d_in[1];
    const float* dminv = (const float*)d_in[2];
    const float* area = (const float*)d_in[3];
    const float* mu_p = (const float*)d_in[4];
    const float* lam_p = (const float*)d_in[5];

    int V = in_sizes[0] / 3;
    int F = in_sizes[1] / 3;

    float* out = (float*)d_out;
    float* per_vert = out + (out_size - V);
    float* loss = (out_size > V) ? out : nullptr;

    cudaMemsetAsync(d_out, 0, (size_t)out_size * sizeof(float));

    int blocks = (F + 255) / 256;
    stvk_face_kernel<<<blocks, 256>>>(pos, faces, dminv, area, mu_p, lam_p,
                                      per_vert, loss, F);
}